// round 12
// baseline (speedup 1.0000x reference)
#include <cuda_runtime.h>

#define BN 8
#define NP 2000
#define NG 100
#define MH 320
#define MW 320
#define NUM_POS 66
#define NUM_NEG 134
#define TRAIN_ROIS 200
#define MASK_H 28
#define MASK_W 28
#define CL 8                       /* CTAs per cluster = per batch */
#define PROPS_PER_CTA (NP/CL)      /* 250 */

// output layout (flattened tuple, float32)
#define ROIS_OFF  0
#define CLS_OFF   (BN*TRAIN_ROIS*4)            /* 6400 */
#define DELTA_OFF (CLS_OFF + BN*TRAIN_ROIS)    /* 8000 */
#define MASK_OFF  (DELTA_OFF + BN*TRAIN_ROIS*4)/* 14400 */

__device__ unsigned g_keyhi[BN*NP];
__device__ int      g_arg[BN*NP];
__device__ unsigned char g_valid[BN*NP];
__device__ int g_poslist[BN*NUM_POS];
__device__ int g_poscount[BN];

// XLA GPU compiles f32 divide with nvptx-prec-divf32=1 -> div.full.f32.
__device__ __forceinline__ float xdiv(float a, float b) {
    float r;
    asm("div.full.f32 %0, %1, %2;" : "=f"(r) : "f"(a), "f"(b));
    return r;
}

__device__ __forceinline__ unsigned orderable(float v) {
    unsigned u = __float_as_uint(v);
    return (u & 0x80000000u) ? ~u : (u | 0x80000000u);
}
// v >= 0.5 <=> hi = ~ord(v) <= ~ord(0.5) = 0x40FFFFFF
__device__ __forceinline__ int pos_hi(unsigned hi) { return hi <= 0x40FFFFFFu; }

#define CLUSTER_SYNC_() do {                                              \
    asm volatile("barrier.cluster.arrive.aligned;" ::: "memory");         \
    asm volatile("barrier.cluster.wait.aligned;" ::: "memory");           \
} while (0)

// ---- register/shuffle bitonic helpers (identical network to smem version) --
__device__ __forceinline__ unsigned long long u64sel(bool keep_min,
                                                     unsigned long long a,
                                                     unsigned long long b) {
    unsigned long long mn = a < b ? a : b;
    unsigned long long mx = a < b ? b : a;
    return keep_min ? mn : mx;
}

template<int K>
__device__ __forceinline__ void warp_phases(unsigned long long &r0,
                                            unsigned long long &r1,
                                            int i0, int i1) {
    #pragma unroll
    for (int j = ((K>>1) < 32 ? (K>>1) : 32); j >= 1; j >>= 1) {
        if (j == 32) {
            bool up = ((i0 & K) == 0);
            if ((r0 > r1) == up) { unsigned long long tmp = r0; r0 = r1; r1 = tmp; }
        } else {
            unsigned long long o0 = __shfl_xor_sync(0xFFFFFFFFu, r0, j);
            bool up0 = ((i0 & K) == 0), lo0 = ((i0 & j) == 0);
            r0 = u64sel(up0 == lo0, r0, o0);
            unsigned long long o1 = __shfl_xor_sync(0xFFFFFFFFu, r1, j);
            bool up1 = ((i1 & K) == 0), lo1 = ((i1 & j) == 0);
            r1 = u64sel(up1 == lo1, r1, o1);
        }
    }
}

// ---------------------------------------------------------------------------
// Single fused kernel: one cluster (8 CTAs x 1024 threads) per batch.
// Phase 1: IoU (all CTAs)  | sync |
// Phase 2: rank0 sort+select+slots, ranks1-7 zero-fill masks | sync |
// Phase 3: all CTAs write bilinear crops for the pc positive slots.
// ---------------------------------------------------------------------------
__global__ __cluster_dims__(CL, 1, 1) __launch_bounds__(1024)
void fused_all(const float4* __restrict__ props,
               const float4* __restrict__ gts,
               const int*    __restrict__ cls,
               const unsigned int* __restrict__ masks,
               float* __restrict__ out)
{
    int b    = blockIdx.x >> 3;    // batch (cluster id)
    int rank = blockIdx.x & 7;     // CTA rank within cluster
    int t    = threadIdx.x;
    int lane = t & 31, wid = t >> 5;

    __shared__ float4 sg[NG];
    __shared__ unsigned char svg[NG];
    __shared__ unsigned long long keys[2048];
    __shared__ unsigned char svalid[2048];
    __shared__ int warpsum[32];
    __shared__ int s_pos[NUM_POS];
    __shared__ int s_neg[NUM_NEG];
    __shared__ int s_cnt[4];

    // ================= Phase 1: IoU for this CTA's 250 proposals ===========
    if (t < NG) {
        float4 q = gts[b*NG + t];
        sg[t] = q;
        svg[t] = (q.x!=0.f)||(q.y!=0.f)||(q.z!=0.f)||(q.w!=0.f);
    }
    __syncthreads();

    {
        int pin  = t >> 2;                       // 0..255 (250 real)
        int sub  = t & 3;
        int live = (pin < PROPS_PER_CTA);
        int pi   = rank*PROPS_PER_CTA + (live ? pin : PROPS_PER_CTA-1);
        int pid  = b*NP + pi;

        float4 p = props[pid];
        unsigned char valid = (p.x!=0.f)||(p.y!=0.f)||(p.z!=0.f)||(p.w!=0.f);
        float area_a = __fmul_rn(__fsub_rn(p.z,p.x), __fsub_rn(p.w,p.y));

        unsigned long long bestk = 0ull;
        int g0 = sub * (NG/4);
        #pragma unroll 5
        for (int gg = 0; gg < NG/4; ++gg) {
            int g = g0 + gg;
            float4 q = sg[g];
            float y1 = fmaxf(p.x, q.x), x1 = fmaxf(p.y, q.y);
            float y2 = fminf(p.z, q.z), x2 = fminf(p.w, q.w);
            float inter = __fmul_rn(fmaxf(__fsub_rn(y2,y1),0.f),
                                    fmaxf(__fsub_rn(x2,x1),0.f));
            float area_b = __fmul_rn(__fsub_rn(q.z,q.x), __fsub_rn(q.w,q.y));
            float uni = __fsub_rn(__fadd_rn(area_a, area_b), inter);
            float iou = xdiv(inter, fmaxf(uni, 1e-8f));
            float v = (svg[g] && valid) ? iou : -1.0f;
            unsigned long long k = (((unsigned long long)orderable(v)) << 32)
                                 | (unsigned)(NG - 1 - g);
            if (k > bestk) bestk = k;
        }

        #pragma unroll
        for (int off = 1; off < 4; off <<= 1) {
            unsigned long long o = __shfl_xor_sync(0xFFFFFFFFu, bestk, off);
            if (o > bestk) bestk = o;
        }

        if (sub == 0 && live) {
            g_keyhi[pid] = ~((unsigned)(bestk >> 32));
            g_arg[pid]   = NG - 1 - (int)(bestk & 0xFFFFFFFFu);
            g_valid[pid] = valid;
        }
    }

    __threadfence();
    CLUSTER_SYNC_();

    // ========= Phase 2: rank0 = sort/select/slots ; ranks1-7 = zero masks ==
    if (rank == 0) {
        // stage validity
        #pragma unroll
        for (int rep = 0; rep < 2; ++rep) {
            int i = t + rep*1024;
            svalid[i] = (i < NP) ? g_valid[b*NP + i] : 0;
        }

        int i0 = wid*64 + lane, i1 = i0 + 32;
        unsigned long long r0 = (i0 < NP)
            ? ((((unsigned long long)g_keyhi[b*NP + i0]) << 32) | (unsigned)i0) : ~0ull;
        unsigned long long r1 = (i1 < NP)
            ? ((((unsigned long long)g_keyhi[b*NP + i1]) << 32) | (unsigned)i1) : ~0ull;

        warp_phases<2>(r0, r1, i0, i1);
        warp_phases<4>(r0, r1, i0, i1);
        warp_phases<8>(r0, r1, i0, i1);
        warp_phases<16>(r0, r1, i0, i1);
        warp_phases<32>(r0, r1, i0, i1);
        warp_phases<64>(r0, r1, i0, i1);

        #define BIG_K(K)                                                      \
        {                                                                     \
            keys[i0] = r0; keys[i1] = r1;                                     \
            __syncthreads();                                                  \
            _Pragma("unroll")                                                 \
            for (int j = (K)>>1; j >= 64; j >>= 1) {                          \
                int i  = ((t & ~(j-1)) << 1) | (t & (j-1));                   \
                int ix = i | j;                                               \
                bool up = ((i & (K)) == 0);                                   \
                unsigned long long a = keys[i], c = keys[ix];                 \
                if ((a > c) == up) { keys[i] = c; keys[ix] = a; }             \
                __syncthreads();                                              \
            }                                                                 \
            r0 = keys[i0]; r1 = keys[i1];                                     \
            warp_phases<K>(r0, r1, i0, i1);                                   \
        }
        BIG_K(128)
        BIG_K(256)
        BIG_K(512)
        BIG_K(1024)
        BIG_K(2048)
        #undef BIG_K

        keys[i0] = r0; keys[i1] = r1;
        __syncthreads();

        // filtered extraction (pass 0: pos, pass 1: neg)
        for (int pass = 0; pass < 2; ++pass) {
            unsigned long long k0 = keys[2*t], k1 = keys[2*t+1];
            unsigned hi0 = (unsigned)(k0 >> 32), hi1 = (unsigned)(k1 >> 32);
            unsigned id0 = (unsigned)(k0 & 0xFFFFFFFFu), id1 = (unsigned)(k1 & 0xFFFFFFFFu);
            int fa, fb;
            if (pass == 0) {
                fa = pos_hi(hi0);
                fb = pos_hi(hi1);
            } else {
                fa = (id0 < NP) && !pos_hi(hi0) && svalid[id0];
                fb = (id1 < NP) && !pos_hi(hi1) && svalid[id1];
            }
            int s = fa + fb;
            int x = s;
            #pragma unroll
            for (int off = 1; off < 32; off <<= 1) {
                int y = __shfl_up_sync(0xFFFFFFFFu, x, off);
                if (lane >= off) x += y;
            }
            if (lane == 31) warpsum[wid] = x;
            __syncthreads();
            if (t < 32) {
                int v = warpsum[t];
                #pragma unroll
                for (int off = 1; off < 32; off <<= 1) {
                    int y = __shfl_up_sync(0xFFFFFFFFu, v, off);
                    if (t >= off) v += y;
                }
                warpsum[t] = v;
            }
            __syncthreads();
            int incl = x + (wid ? warpsum[wid-1] : 0);
            int excl = incl - s;
            if (pass == 0) {
                if (fa && excl < NUM_POS)        s_pos[excl]      = (int)id0;
                if (fb && (excl + fa) < NUM_POS) s_pos[excl + fa] = (int)id1;
            } else {
                if (fa && excl < NUM_NEG)        s_neg[excl]      = (int)id0;
                if (fb && (excl + fa) < NUM_NEG) s_neg[excl + fa] = (int)id1;
            }
            if (t == 0) s_cnt[pass] = warpsum[31];
            __syncthreads();
        }

        if (t == 0) {
            int pc = min(s_cnt[0], NUM_POS);
            int nc = (int)xdiv((float)pc, 0.33f) - pc;   // reference's div.full
            nc = min(nc, s_cnt[1]);
            nc = min(nc, NUM_NEG);
            if (nc < 0) nc = 0;
            s_cnt[2] = pc;
            s_cnt[3] = nc;
            g_poscount[b] = pc;
        }
        __syncthreads();
        int pc = s_cnt[2], nc = s_cnt[3];

        if (t < NUM_POS && t < pc) g_poslist[b*NUM_POS + t] = s_pos[t];

        // slots tail: rois / class / deltas for all 200 slots
        if (t < TRAIN_ROIS) {
            float4 roi = make_float4(0.f,0.f,0.f,0.f);
            float  c   = 0.f;
            float4 dd  = make_float4(0.f,0.f,0.f,0.f);

            if (t < NUM_POS) {
                if (t < pc) {
                    int p = s_pos[t];
                    float4 r = props[b*NP + p];
                    roi = r;
                    int g = g_arg[b*NP + p];
                    c = (float)cls[b*NG + g];
                    float4 q = gts[b*NG + g];
                    float h  = fmaxf(__fsub_rn(r.z,r.x), 1e-8f);
                    float w  = fmaxf(__fsub_rn(r.w,r.y), 1e-8f);
                    float cy = __fadd_rn(r.x, __fmul_rn(0.5f,h));
                    float cx = __fadd_rn(r.y, __fmul_rn(0.5f,w));
                    float gh  = fmaxf(__fsub_rn(q.z,q.x), 1e-8f);
                    float gw  = fmaxf(__fsub_rn(q.w,q.y), 1e-8f);
                    float gcy = __fadd_rn(q.x, __fmul_rn(0.5f,gh));
                    float gcx = __fadd_rn(q.y, __fmul_rn(0.5f,gw));
                    dd.x = xdiv(xdiv(__fsub_rn(gcy,cy), h), 0.1f);
                    dd.y = xdiv(xdiv(__fsub_rn(gcx,cx), w), 0.1f);
                    dd.z = xdiv(logf(xdiv(gh,h)), 0.2f);
                    dd.w = xdiv(logf(xdiv(gw,w)), 0.2f);
                }
            } else {
                int j = t - NUM_POS;
                if (j < nc) {
                    int p = s_neg[j];
                    roi = props[b*NP + p];
                }
            }

            ((float4*)(out + ROIS_OFF))[b*TRAIN_ROIS + t]  = roi;
            out[CLS_OFF + b*TRAIN_ROIS + t]                = c;
            ((float4*)(out + DELTA_OFF))[b*TRAIN_ROIS + t] = dd;
        }
    } else {
        // ranks 1..7: zero-fill this batch's whole mask region (float4 stores)
        float4 z = make_float4(0.f,0.f,0.f,0.f);
        float4* mz = (float4*)(out + MASK_OFF + (size_t)b*TRAIN_ROIS*(MASK_H*MASK_W));
        const int total4 = TRAIN_ROIS*MASK_H*MASK_W/4;   // 39200
        for (int i = (rank-1)*1024 + t; i < total4; i += 7*1024)
            mz[i] = z;
    }

    __threadfence();
    CLUSTER_SYNC_();

    // ========= Phase 3: all CTAs write crops for the pc positive slots =====
    int pc = g_poscount[b];
    int total = pc * (MASK_H*MASK_W);
    for (int e = rank*1024 + t; e < total; e += CL*1024) {
        int i  = e / (MASK_H*MASK_W);
        int px = e - i*(MASK_H*MASK_W);
        int y = px / MASK_W, x = px % MASK_W;

        int p = g_poslist[b*NUM_POS + i];
        float4 r = props[b*NP + p];
        int g = g_arg[b*NP + p];

        float fy = xdiv((float)y, (float)(MASK_H-1));
        float fx = xdiv((float)x, (float)(MASK_W-1));
        float sy = __fadd_rn(__fmul_rn(r.x, 319.f),
                             __fmul_rn(__fmul_rn(fy, __fsub_rn(r.z,r.x)), 319.f));
        sy = fminf(fmaxf(sy, 0.f), 319.f);
        float sx = __fadd_rn(__fmul_rn(r.y, 319.f),
                             __fmul_rn(__fmul_rn(fx, __fsub_rn(r.w,r.y)), 319.f));
        sx = fminf(fmaxf(sx, 0.f), 319.f);

        int y0 = min(max((int)floorf(sy), 0), MH-2);
        int x0 = min(max((int)floorf(sx), 0), MW-2);
        float wy = __fsub_rn(sy, (float)y0);
        float wx = __fsub_rn(sx, (float)x0);

        size_t i00 = (((size_t)b*MH + y0)*MW + x0)*NG + g;
        float c00 = masks[i00]                    ? 1.f : 0.f;
        float c01 = masks[i00 + NG]               ? 1.f : 0.f;
        float c10 = masks[i00 + (size_t)MW*NG]    ? 1.f : 0.f;
        float c11 = masks[i00 + (size_t)MW*NG+NG] ? 1.f : 0.f;

        float top = __fadd_rn(__fmul_rn(c00, __fsub_rn(1.f,wx)), __fmul_rn(c01, wx));
        float bot = __fadd_rn(__fmul_rn(c10, __fsub_rn(1.f,wx)), __fmul_rn(c11, wx));
        float val = __fadd_rn(__fmul_rn(top, __fsub_rn(1.f,wy)), __fmul_rn(bot, wy));

        out[MASK_OFF + ((size_t)b*TRAIN_ROIS + i)*(MASK_H*MASK_W) + px] = rintf(val);
    }
}

// ---------------------------------------------------------------------------
extern "C" void kernel_launch(void* const* d_in, const int* in_sizes, int n_in,
                              void* d_out, int out_size)
{
    const float4*       props = 0;
    const int*          cls   = 0;
    const float4*       gts   = 0;
    const unsigned int* masks = 0;
    for (int i = 0; i < n_in; ++i) {
        switch (in_sizes[i]) {
            case BN*NP*4:              props = (const float4*)d_in[i];       break;
            case BN*NG:                cls   = (const int*)d_in[i];          break;
            case BN*NG*4:              gts   = (const float4*)d_in[i];       break;
            default:                   masks = (const unsigned int*)d_in[i]; break;
        }
    }
    float* out = (float*)d_out;

    fused_all<<<BN*CL, 1024>>>(props, gts, cls, masks, out);
}